// round 2
// baseline (speedup 1.0000x reference)
#include <cuda_runtime.h>
#include <mma.h>
#include <cstdint>

using namespace nvcuda;

#define TSEQ 2048
#define CEMB 4096
#define QKVN 6144
#define FFNN 11008
#define NHEAD 32
#define NGRP 8
#define HSZ 128

// ------------------------- scratch (device globals) -------------------------
__device__ float g_n1[TSEQ * CEMB];
__device__ float g_qkv[TSEQ * QKVN];
__device__ float g_scaling[TSEQ * CEMB];
__device__ float g_scale_t[NHEAD * TSEQ];
__device__ float g_q[NHEAD * TSEQ * HSZ];
__device__ float g_k[NGRP * TSEQ * HSZ];
__device__ float g_v[NGRP * TSEQ * HSZ];
__device__ float g_scores[134217728];            // 32 * 2048 * 2048
__device__ float g_y[TSEQ * CEMB];
__device__ float g_x2[TSEQ * CEMB];
__device__ float g_n2[TSEQ * CEMB];
__device__ float g_gate[TSEQ * FFNN];
__device__ float g_up[TSEQ * FFNN];

// ------------------------- GEMM (tf32 wmma) -------------------------
// C[M,N] = A[M,K] * op(B)
//   TB=true : B is [N,K] row-major (B^T math)  -> NT
//   TB=false: B is [K,N] row-major             -> NN
// Batched over blockIdx.z with element strides sA,sB,sC; B batch index = z / bDiv.

#define BM 128
#define BN 128
#define BK 32
#define ALD 40      // padded ld for [*][BK] tiles
#define BLDNN 136   // padded ld for [BK][BN] tile (NN)

template <bool TB>
__global__ void __launch_bounds__(256) gemm_kernel(
    const float* __restrict__ A, const float* __restrict__ B, float* __restrict__ C,
    int M, int N, int K, int ldc,
    long long sA, long long sB, long long sC, int bDiv)
{
    __shared__ __align__(16) float sm[5120 + 5120];
    float* As = sm;
    float* Bs = sm + 5120;

    const int z = blockIdx.z;
    A += (long long)z * sA;
    B += (long long)(z / bDiv) * sB;
    C += (long long)z * sC;

    const int m0 = blockIdx.y * BM;
    const int n0 = blockIdx.x * BN;
    const int tid = threadIdx.x;
    const int warp = tid >> 5;
    const int wr = warp >> 2;   // 0..1
    const int wc = warp & 3;    // 0..3

    wmma::fragment<wmma::accumulator, 16, 16, 8, float> acc[4][2];
#pragma unroll
    for (int i = 0; i < 4; i++)
#pragma unroll
        for (int j = 0; j < 2; j++) wmma::fill_fragment(acc[i][j], 0.0f);

    for (int k0 = 0; k0 < K; k0 += BK) {
        // load A tile [BM][BK]
#pragma unroll
        for (int it = 0; it < 4; it++) {
            int idx = tid + it * 256;
            int r = idx >> 3;
            int c = (idx & 7) << 2;
            *(float4*)(As + r * ALD + c) =
                *(const float4*)(A + (long long)(m0 + r) * K + k0 + c);
        }
        if (TB) {
            // B tile [BN][BK]
#pragma unroll
            for (int it = 0; it < 4; it++) {
                int idx = tid + it * 256;
                int r = idx >> 3;
                int c = (idx & 7) << 2;
                *(float4*)(Bs + r * ALD + c) =
                    *(const float4*)(B + (long long)(n0 + r) * K + k0 + c);
            }
        } else {
            // B tile [BK][BN]
#pragma unroll
            for (int it = 0; it < 4; it++) {
                int idx = tid + it * 256;
                int r = idx >> 5;
                int c = (idx & 31) << 2;
                *(float4*)(Bs + r * BLDNN + c) =
                    *(const float4*)(B + (long long)(k0 + r) * N + n0 + c);
            }
        }
        __syncthreads();

#pragma unroll
        for (int kk = 0; kk < 4; kk++) {
            wmma::fragment<wmma::matrix_a, 16, 16, 8, wmma::precision::tf32, wmma::row_major> fa[4];
#pragma unroll
            for (int i = 0; i < 4; i++) {
                wmma::load_matrix_sync(fa[i], As + (wr * 64 + i * 16) * ALD + kk * 8, ALD);
#pragma unroll
                for (int e = 0; e < fa[i].num_elements; e++)
                    fa[i].x[e] = wmma::__float_to_tf32(fa[i].x[e]);
            }
            if (TB) {
                wmma::fragment<wmma::matrix_b, 16, 16, 8, wmma::precision::tf32, wmma::col_major> fb[2];
#pragma unroll
                for (int j = 0; j < 2; j++) {
                    wmma::load_matrix_sync(fb[j], Bs + (wc * 32 + j * 16) * ALD + kk * 8, ALD);
#pragma unroll
                    for (int e = 0; e < fb[j].num_elements; e++)
                        fb[j].x[e] = wmma::__float_to_tf32(fb[j].x[e]);
                }
#pragma unroll
                for (int i = 0; i < 4; i++)
#pragma unroll
                    for (int j = 0; j < 2; j++)
                        wmma::mma_sync(acc[i][j], fa[i], fb[j], acc[i][j]);
            } else {
                wmma::fragment<wmma::matrix_b, 16, 16, 8, wmma::precision::tf32, wmma::row_major> fb[2];
#pragma unroll
                for (int j = 0; j < 2; j++) {
                    wmma::load_matrix_sync(fb[j], Bs + (kk * 8) * BLDNN + wc * 32 + j * 16, BLDNN);
#pragma unroll
                    for (int e = 0; e < fb[j].num_elements; e++)
                        fb[j].x[e] = wmma::__float_to_tf32(fb[j].x[e]);
                }
#pragma unroll
                for (int i = 0; i < 4; i++)
#pragma unroll
                    for (int j = 0; j < 2; j++)
                        wmma::mma_sync(acc[i][j], fa[i], fb[j], acc[i][j]);
            }
        }
        __syncthreads();
    }

#pragma unroll
    for (int i = 0; i < 4; i++)
#pragma unroll
        for (int j = 0; j < 2; j++)
            wmma::store_matrix_sync(
                C + (long long)(m0 + wr * 64 + i * 16) * ldc + n0 + wc * 32 + j * 16,
                acc[i][j], ldc, wmma::mem_row_major);
}

// ------------------------- small kernels -------------------------

__global__ void rmsnorm_kernel(const float* __restrict__ x, const float* __restrict__ w,
                               float* __restrict__ out)
{
    __shared__ float red[256];
    const int t = blockIdx.x;
    const float* row = x + (size_t)t * CEMB;
    float* orow = out + (size_t)t * CEMB;
    const int tid = threadIdx.x;
    float s = 0.f;
    for (int i = tid; i < CEMB; i += 256) { float v = row[i]; s += v * v; }
    red[tid] = s;
    __syncthreads();
    for (int st = 128; st > 0; st >>= 1) {
        if (tid < st) red[tid] += red[tid + st];
        __syncthreads();
    }
    const float inv = rsqrtf(red[0] * (1.0f / CEMB) + 1e-5f);
    for (int i = tid; i < CEMB; i += 256) orow[i] = row[i] * inv * w[i];
}

__global__ void bias_relu_kernel(float* __restrict__ a, const float* __restrict__ b)
{
    const int i = blockIdx.x * 256 + threadIdx.x;
    a[i] = fmaxf(a[i] + b[i & (CEMB - 1)], 0.f);
}

__global__ void scale_reduce_kernel(const float* __restrict__ s, float* __restrict__ st)
{
    const int pair = blockIdx.x * 8 + (threadIdx.x >> 5);  // = t*32 + h
    const int lane = threadIdx.x & 31;
    const int t = pair >> 5;
    const int h = pair & 31;
    const float* p = s + (size_t)t * CEMB + h * HSZ;
    float acc = 0.f;
    for (int d = lane; d < HSZ; d += 32) acc += p[d];
    for (int o = 16; o; o >>= 1) acc += __shfl_down_sync(0xffffffffu, acc, o);
    if (lane == 0) st[h * TSEQ + t] = acc * (1.0f / HSZ);
}

// split qkv into q/k/v layouts, apply RoPE, fold sf*scale_t into q rows
__global__ void qkv_rope_kernel(const float* __restrict__ qkv, const float* __restrict__ cs,
                                const float* __restrict__ sn, const float* __restrict__ st,
                                float* __restrict__ q, float* __restrict__ k,
                                float* __restrict__ v)
{
    const int idx = blockIdx.x * 256 + threadIdx.x;
    const int d = idx & 127;
    const int rest = idx >> 7;
    const int slot = rest % 48;
    const int t = rest / 48;
    const int g = slot / 6;
    const int i = slot % 6;
    const float* src = qkv + (size_t)t * QKVN + g * 768 + i * 128;
    const float x0 = src[d];
    if (i == 5) {
        v[((size_t)g * TSEQ + t) * HSZ + d] = x0;
        return;
    }
    const float xp = src[d ^ 64];
    const float rot = (d < 64) ? -xp : xp;
    const float val = x0 * cs[t * 128 + d] + rot * sn[t * 128 + d];
    if (i == 4) {
        k[((size_t)g * TSEQ + t) * HSZ + d] = val;
    } else {
        const int h = g * 4 + i;
        q[((size_t)h * TSEQ + t) * HSZ + d] =
            val * (0.08838834764831845f * st[h * TSEQ + t]);  // 1/sqrt(128) * scale_t
    }
}

__global__ void softmax_kernel(float* __restrict__ scores)
{
    __shared__ float red[256];
    const size_t row = blockIdx.x;
    float* p = scores + row * TSEQ;
    const int tid = threadIdx.x;

    float m = -1e30f;
    for (int i = tid; i < TSEQ; i += 256) m = fmaxf(m, p[i]);
    red[tid] = m;
    __syncthreads();
    for (int st = 128; st > 0; st >>= 1) {
        if (tid < st) red[tid] = fmaxf(red[tid], red[tid + st]);
        __syncthreads();
    }
    m = red[0];
    __syncthreads();

    float sum = 0.f;
    for (int i = tid; i < TSEQ; i += 256) {
        float e = __expf(p[i] - m);
        p[i] = e;
        sum += e;
    }
    red[tid] = sum;
    __syncthreads();
    for (int st = 128; st > 0; st >>= 1) {
        if (tid < st) red[tid] += red[tid + st];
        __syncthreads();
    }
    const float inv = 1.f / red[0];
    for (int i = tid; i < TSEQ; i += 256) p[i] *= inv;
}

__global__ void silu_mul_kernel(float* __restrict__ g, const float* __restrict__ u)
{
    const int i = blockIdx.x * 256 + threadIdx.x;
    const float x = g[i];
    g[i] = (x / (1.f + __expf(-x))) * u[i];
}

__global__ void add_kernel(float* __restrict__ a, const float* __restrict__ b)
{
    const int i = blockIdx.x * 256 + threadIdx.x;
    a[i] += b[i];
}

// ------------------------- host side -------------------------

static inline void gemm_nt(const float* A, const float* B, float* C, int M, int N, int K,
                           int ldc, long long sA, long long sB, long long sC, int bDiv, int nb)
{
    dim3 grid(N / BN, M / BM, nb);
    gemm_kernel<true><<<grid, 256>>>(A, B, C, M, N, K, ldc, sA, sB, sC, bDiv);
}

static inline void gemm_nn(const float* A, const float* B, float* C, int M, int N, int K,
                           int ldc, long long sA, long long sB, long long sC, int bDiv, int nb)
{
    dim3 grid(N / BN, M / BM, nb);
    gemm_kernel<false><<<grid, 256>>>(A, B, C, M, N, K, ldc, sA, sB, sC, bDiv);
}

extern "C" void kernel_launch(void* const* d_in, const int* in_sizes, int n_in,
                              void* d_out, int out_size)
{
    (void)in_sizes; (void)n_in; (void)out_size;
    const float* x       = (const float*)d_in[0];
    const float* cosp    = (const float*)d_in[1];
    const float* sinp    = (const float*)d_in[2];
    const float* n1w     = (const float*)d_in[3];
    const float* n2w     = (const float*)d_in[4];
    const float* attn_w  = (const float*)d_in[5];
    const float* proj_w  = (const float*)d_in[6];
    const float* scale_w = (const float*)d_in[7];
    const float* scale_b = (const float*)d_in[8];
    const float* gate_w  = (const float*)d_in[9];
    const float* up_w    = (const float*)d_in[10];
    const float* down_w  = (const float*)d_in[11];
    float* out = (float*)d_out;

    float *p_n1, *p_qkv, *p_scaling, *p_st, *p_q, *p_k, *p_v, *p_sc, *p_y, *p_x2, *p_n2,
        *p_gate, *p_up;
    cudaGetSymbolAddress((void**)&p_n1, g_n1);
    cudaGetSymbolAddress((void**)&p_qkv, g_qkv);
    cudaGetSymbolAddress((void**)&p_scaling, g_scaling);
    cudaGetSymbolAddress((void**)&p_st, g_scale_t);
    cudaGetSymbolAddress((void**)&p_q, g_q);
    cudaGetSymbolAddress((void**)&p_k, g_k);
    cudaGetSymbolAddress((void**)&p_v, g_v);
    cudaGetSymbolAddress((void**)&p_sc, g_scores);
    cudaGetSymbolAddress((void**)&p_y, g_y);
    cudaGetSymbolAddress((void**)&p_x2, g_x2);
    cudaGetSymbolAddress((void**)&p_n2, g_n2);
    cudaGetSymbolAddress((void**)&p_gate, g_gate);
    cudaGetSymbolAddress((void**)&p_up, g_up);

    // 1. n1 = rmsnorm(x)
    rmsnorm_kernel<<<TSEQ, 256>>>(x, n1w, p_n1);
    // 2. qkv = n1 @ attn_w^T
    gemm_nt(p_n1, attn_w, p_qkv, TSEQ, QKVN, CEMB, QKVN, 0, 0, 0, 1, 1);
    // 3. scaling = n1 @ scale_w^T ; relu(+bias)
    gemm_nt(p_n1, scale_w, p_scaling, TSEQ, CEMB, CEMB, CEMB, 0, 0, 0, 1, 1);
    bias_relu_kernel<<<TSEQ * CEMB / 256, 256>>>(p_scaling, scale_b);
    // 4. scale_t[h][t] = mean over head dims
    scale_reduce_kernel<<<TSEQ * NHEAD / 8, 256>>>(p_scaling, p_st);
    // 5. split + rope, fold sf*scale_t into q
    qkv_rope_kernel<<<TSEQ * 48 * HSZ / 256, 256>>>(p_qkv, cosp, sinp, p_st, p_q, p_k, p_v);
    // 6. scores[h] = q[h] @ k[h/4]^T
    gemm_nt(p_q, p_k, p_sc, TSEQ, TSEQ, HSZ, TSEQ,
            (long long)TSEQ * HSZ, (long long)TSEQ * HSZ, (long long)TSEQ * TSEQ, 4, NHEAD);
    // 7. softmax rows
    softmax_kernel<<<NHEAD * TSEQ, 256>>>(p_sc);
    // 8. y[h] = attn[h] @ v[h/4]  (written interleaved into [t, h*128+d])
    gemm_nn(p_sc, p_v, p_y, TSEQ, HSZ, TSEQ, CEMB,
            (long long)TSEQ * TSEQ, (long long)TSEQ * HSZ, HSZ, 4, NHEAD);
    // 9. x2 = y @ proj_w^T + x
    gemm_nt(p_y, proj_w, p_x2, TSEQ, CEMB, CEMB, CEMB, 0, 0, 0, 1, 1);
    add_kernel<<<TSEQ * CEMB / 256, 256>>>(p_x2, x);
    // 10. n2 = rmsnorm(x2)
    rmsnorm_kernel<<<TSEQ, 256>>>(p_x2, n2w, p_n2);
    // 11. gate/up GEMMs + silu*mul
    gemm_nt(p_n2, gate_w, p_gate, TSEQ, FFNN, CEMB, FFNN, 0, 0, 0, 1, 1);
    gemm_nt(p_n2, up_w, p_up, TSEQ, FFNN, CEMB, FFNN, 0, 0, 0, 1, 1);
    silu_mul_kernel<<<TSEQ * FFNN / 256, 256>>>(p_gate, p_up);
    // 12. out = act @ down_w^T + x2
    gemm_nt(p_gate, down_w, out, TSEQ, CEMB, FFNN, CEMB, 0, 0, 0, 1, 1);
    add_kernel<<<TSEQ * CEMB / 256, 256>>>(out, p_x2);
}

// round 6
// speedup vs baseline: 1.5256x; 1.5256x over previous
#include <cuda_runtime.h>
#include <mma.h>
#include <cstdint>

using namespace nvcuda;

#define TSEQ 2048
#define CEMB 4096
#define QKVN 6144
#define FFNN 11008
#define NHEAD 32
#define NGRP 8
#define HSZ 128

// ------------------------- scratch (device globals) -------------------------
__device__ float g_n1[TSEQ * CEMB];
__device__ float g_qkv[TSEQ * QKVN];
__device__ float g_scaling[TSEQ * CEMB];
__device__ float g_scale_t[NHEAD * TSEQ];
__device__ float g_invsum[NHEAD * TSEQ];
__device__ float g_q[NHEAD * TSEQ * HSZ];
__device__ float g_k[NGRP * TSEQ * HSZ];
__device__ float g_v[NGRP * TSEQ * HSZ];
__device__ float g_scores[134217728];            // 32 * 2048 * 2048
__device__ float g_y[TSEQ * CEMB];
__device__ float g_x2[TSEQ * CEMB];
__device__ float g_n2[TSEQ * CEMB];
__device__ float g_gate[TSEQ * FFNN];
__device__ float g_up[TSEQ * FFNN];

// ------------------------- cp.async helpers -------------------------
__device__ __forceinline__ void cp_async16(float* smem, const float* gmem)
{
    uint32_t s = (uint32_t)__cvta_generic_to_shared(smem);
    asm volatile("cp.async.cg.shared.global [%0], [%1], 16;\n" :: "r"(s), "l"(gmem));
}
#define CP_COMMIT asm volatile("cp.async.commit_group;\n" ::: "memory")
#define CP_WAIT0  asm volatile("cp.async.wait_group 0;\n" ::: "memory")
#define CP_WAIT1  asm volatile("cp.async.wait_group 1;\n" ::: "memory")

// ------------------------- GEMM (tf32 wmma, 2-stage cp.async) -------------------------
// C[M,N] = A[M,K] * op(B)  (+ epilogue)
//   TB=true : B is [N,K] row-major (B^T)   TB=false: B is [K,N] row-major
// EPI: 0=none  1=C+=ep[gm*ldc+gn]  2=C=relu(C+ep[gn])  3=C*=ep[z*M+gm]
#define BM 128
#define BN 128
#define BK 32
#define ALD 40
#define BLDNN 136
#define STAGE_F 10240           // floats per pipeline stage (As 5120 + Bs 5120)
#define GEMM_SMEM_BYTES 81920   // 2 stages * 10240 * 4
#define SLD 36                  // epilogue staging ld: MUST be multiple of 4 (wmma fp32)

template <bool TB, int EPI>
__global__ void __launch_bounds__(256, 2) gemm_kernel(
    const float* __restrict__ A, const float* __restrict__ B, float* __restrict__ C,
    const float* __restrict__ ep,
    int M, int N, int K, int ldc,
    long long sA, long long sB, long long sC, int bDiv)
{
    extern __shared__ __align__(16) float sm[];

    const int z = blockIdx.z;
    A += (long long)z * sA;
    B += (long long)(z / bDiv) * sB;
    C += (long long)z * sC;

    const int m0 = blockIdx.y * BM;
    const int n0 = blockIdx.x * BN;
    const int tid = threadIdx.x;
    const int lane = tid & 31;
    const int warp = tid >> 5;
    const int wr = warp >> 2;   // 0..1
    const int wc = warp & 3;    // 0..3

    const int ar = tid >> 3, ac = (tid & 7) << 2;     // [128][32] tile loads
    const int br = tid >> 5, bc = (tid & 31) << 2;    // [32][128] tile loads (NN)

    wmma::fragment<wmma::accumulator, 16, 16, 8, float> acc[4][2];
#pragma unroll
    for (int i = 0; i < 4; i++)
#pragma unroll
        for (int j = 0; j < 2; j++) wmma::fill_fragment(acc[i][j], 0.0f);

    const int KT = K >> 5;

    auto load_tile = [&](int kt, int st) {
        float* As = sm + st * STAGE_F;
        float* Bs = As + 5120;
        const int k0 = kt << 5;
#pragma unroll
        for (int it = 0; it < 4; it++) {
            int r = ar + it * 32;
            cp_async16(As + r * ALD + ac, A + (long long)(m0 + r) * K + k0 + ac);
        }
        if (TB) {
#pragma unroll
            for (int it = 0; it < 4; it++) {
                int r = ar + it * 32;
                cp_async16(Bs + r * ALD + ac, B + (long long)(n0 + r) * K + k0 + ac);
            }
        } else {
#pragma unroll
            for (int it = 0; it < 4; it++) {
                int r = br + it * 8;
                cp_async16(Bs + r * BLDNN + bc, B + (long long)(k0 + r) * N + n0 + bc);
            }
        }
    };

    load_tile(0, 0);
    CP_COMMIT;

    for (int kt = 0; kt < KT; kt++) {
        const int cur = kt & 1;
        if (kt + 1 < KT) {
            load_tile(kt + 1, cur ^ 1);
            CP_COMMIT;
            CP_WAIT1;
        } else {
            CP_WAIT0;
        }
        __syncthreads();

        float* As = sm + cur * STAGE_F;
        float* Bs = As + 5120;
#pragma unroll
        for (int kk = 0; kk < 4; kk++) {
            wmma::fragment<wmma::matrix_a, 16, 16, 8, wmma::precision::tf32, wmma::row_major> fa[4];
#pragma unroll
            for (int i = 0; i < 4; i++) {
                wmma::load_matrix_sync(fa[i], As + (wr * 64 + i * 16) * ALD + kk * 8, ALD);
#pragma unroll
                for (int e = 0; e < fa[i].num_elements; e++)
                    fa[i].x[e] = wmma::__float_to_tf32(fa[i].x[e]);
            }
            if (TB) {
                wmma::fragment<wmma::matrix_b, 16, 16, 8, wmma::precision::tf32, wmma::col_major> fb[2];
#pragma unroll
                for (int j = 0; j < 2; j++) {
                    wmma::load_matrix_sync(fb[j], Bs + (wc * 32 + j * 16) * ALD + kk * 8, ALD);
#pragma unroll
                    for (int e = 0; e < fb[j].num_elements; e++)
                        fb[j].x[e] = wmma::__float_to_tf32(fb[j].x[e]);
                }
#pragma unroll
                for (int i = 0; i < 4; i++)
#pragma unroll
                    for (int j = 0; j < 2; j++)
                        wmma::mma_sync(acc[i][j], fa[i], fb[j], acc[i][j]);
            } else {
                wmma::fragment<wmma::matrix_b, 16, 16, 8, wmma::precision::tf32, wmma::row_major> fb[2];
#pragma unroll
                for (int j = 0; j < 2; j++) {
                    wmma::load_matrix_sync(fb[j], Bs + (kk * 8) * BLDNN + wc * 32 + j * 16, BLDNN);
#pragma unroll
                    for (int e = 0; e < fb[j].num_elements; e++)
                        fb[j].x[e] = wmma::__float_to_tf32(fb[j].x[e]);
                }
#pragma unroll
                for (int i = 0; i < 4; i++)
#pragma unroll
                    for (int j = 0; j < 2; j++)
                        wmma::mma_sync(acc[i][j], fa[i], fb[j], acc[i][j]);
            }
        }
        __syncthreads();
    }

    // ---- epilogue via smem staging (64 x SLD per warp; SLD % 4 == 0) ----
    float* stg = sm + warp * (64 * SLD);
#pragma unroll
    for (int i = 0; i < 4; i++)
#pragma unroll
        for (int j = 0; j < 2; j++)
            wmma::store_matrix_sync(stg + (i * 16) * SLD + j * 16, acc[i][j], SLD,
                                    wmma::mem_row_major);
    __syncwarp();

    const int gn = n0 + wc * 32 + lane;
#pragma unroll 4
    for (int r = 0; r < 64; r++) {
        const int gm = m0 + wr * 64 + r;
        float v = stg[r * SLD + lane];
        if (EPI == 1) v += ep[(long long)gm * ldc + gn];
        if (EPI == 2) v = fmaxf(v + ep[gn], 0.0f);
        if (EPI == 3) v *= ep[(long long)z * M + gm];
        C[(long long)gm * ldc + gn] = v;
    }
}

// ------------------------- small kernels -------------------------

__global__ void rmsnorm_kernel(const float* __restrict__ x, const float* __restrict__ w,
                               float* __restrict__ out)
{
    __shared__ float red[256];
    const int t = blockIdx.x;
    const float* row = x + (size_t)t * CEMB;
    float* orow = out + (size_t)t * CEMB;
    const int tid = threadIdx.x;
    float s = 0.f;
    for (int i = tid; i < CEMB; i += 256) { float v = row[i]; s += v * v; }
    red[tid] = s;
    __syncthreads();
    for (int st = 128; st > 0; st >>= 1) {
        if (tid < st) red[tid] += red[tid + st];
        __syncthreads();
    }
    const float inv = rsqrtf(red[0] * (1.0f / CEMB) + 1e-5f);
    for (int i = tid; i < CEMB; i += 256) orow[i] = row[i] * inv * w[i];
}

__global__ void scale_reduce_kernel(const float* __restrict__ s, float* __restrict__ st)
{
    const int pair = blockIdx.x * 8 + (threadIdx.x >> 5);  // = t*32 + h
    const int lane = threadIdx.x & 31;
    const int t = pair >> 5;
    const int h = pair & 31;
    const float* p = s + (size_t)t * CEMB + h * HSZ;
    float acc = 0.f;
    for (int d = lane; d < HSZ; d += 32) acc += p[d];
    for (int o = 16; o; o >>= 1) acc += __shfl_down_sync(0xffffffffu, acc, o);
    if (lane == 0) st[h * TSEQ + t] = acc * (1.0f / HSZ);
}

__global__ void qkv_rope_kernel(const float* __restrict__ qkv, const float* __restrict__ cs,
                                const float* __restrict__ sn, const float* __restrict__ st,
                                float* __restrict__ q, float* __restrict__ k,
                                float* __restrict__ v)
{
    const int idx = blockIdx.x * 256 + threadIdx.x;
    const int d = idx & 127;
    const int rest = idx >> 7;
    const int slot = rest % 48;
    const int t = rest / 48;
    const int g = slot / 6;
    const int i = slot % 6;
    const float* src = qkv + (size_t)t * QKVN + g * 768 + i * 128;
    const float x0 = src[d];
    if (i == 5) {
        v[((size_t)g * TSEQ + t) * HSZ + d] = x0;
        return;
    }
    const float xp = src[d ^ 64];
    const float rot = (d < 64) ? -xp : xp;
    const float val = x0 * cs[t * 128 + d] + rot * sn[t * 128 + d];
    if (i == 4) {
        k[((size_t)g * TSEQ + t) * HSZ + d] = val;
    } else {
        const int h = g * 4 + i;
        q[((size_t)h * TSEQ + t) * HSZ + d] =
            val * (0.08838834764831845f * st[h * TSEQ + t]);  // 1/sqrt(128)*scale_t
    }
}

// 2-pass softmax: exp(x - max) in place; 1/sum written for AV-gemm epilogue
__global__ void softmax_kernel(float* __restrict__ scores, float* __restrict__ invsum)
{
    __shared__ float red[256];
    const size_t row = blockIdx.x;
    float* p = scores + row * TSEQ;
    const int tid = threadIdx.x;

    float m = -1e30f;
    for (int i = tid; i < TSEQ; i += 256) m = fmaxf(m, p[i]);
    red[tid] = m;
    __syncthreads();
    for (int st = 128; st > 0; st >>= 1) {
        if (tid < st) red[tid] = fmaxf(red[tid], red[tid + st]);
        __syncthreads();
    }
    m = red[0];
    __syncthreads();

    float sum = 0.f;
    for (int i = tid; i < TSEQ; i += 256) {
        float e = __expf(p[i] - m);
        p[i] = e;
        sum += e;
    }
    red[tid] = sum;
    __syncthreads();
    for (int st = 128; st > 0; st >>= 1) {
        if (tid < st) red[tid] += red[tid + st];
        __syncthreads();
    }
    if (tid == 0) invsum[row] = 1.f / red[0];
}

__global__ void silu_mul_kernel(float* __restrict__ g, const float* __restrict__ u)
{
    const int i = blockIdx.x * 256 + threadIdx.x;
    const float x = g[i];
    g[i] = (x / (1.f + __expf(-x))) * u[i];
}

// ------------------------- host side -------------------------

template <bool TB, int EPI>
static inline void run_gemm(const float* A, const float* B, float* C, const float* ep,
                            int M, int N, int K, int ldc,
                            long long sA, long long sB, long long sC, int bDiv, int nb)
{
    cudaFuncSetAttribute(gemm_kernel<TB, EPI>,
                         cudaFuncAttributeMaxDynamicSharedMemorySize, GEMM_SMEM_BYTES);
    dim3 grid(N / BN, M / BM, nb);
    gemm_kernel<TB, EPI><<<grid, 256, GEMM_SMEM_BYTES>>>(A, B, C, ep, M, N, K, ldc,
                                                         sA, sB, sC, bDiv);
}

extern "C" void kernel_launch(void* const* d_in, const int* in_sizes, int n_in,
                              void* d_out, int out_size)
{
    (void)in_sizes; (void)n_in; (void)out_size;
    const float* x       = (const float*)d_in[0];
    const float* cosp    = (const float*)d_in[1];
    const float* sinp    = (const float*)d_in[2];
    const float* n1w     = (const float*)d_in[3];
    const float* n2w     = (const float*)d_in[4];
    const float* attn_w  = (const float*)d_in[5];
    const float* proj_w  = (const float*)d_in[6];
    const float* scale_w = (const float*)d_in[7];
    const float* scale_b = (const float*)d_in[8];
    const float* gate_w  = (const float*)d_in[9];
    const float* up_w    = (const float*)d_in[10];
    const float* down_w  = (const float*)d_in[11];
    float* out = (float*)d_out;

    float *p_n1, *p_qkv, *p_scaling, *p_st, *p_is, *p_q, *p_k, *p_v, *p_sc, *p_y, *p_x2,
        *p_n2, *p_gate, *p_up;
    cudaGetSymbolAddress((void**)&p_n1, g_n1);
    cudaGetSymbolAddress((void**)&p_qkv, g_qkv);
    cudaGetSymbolAddress((void**)&p_scaling, g_scaling);
    cudaGetSymbolAddress((void**)&p_st, g_scale_t);
    cudaGetSymbolAddress((void**)&p_is, g_invsum);
    cudaGetSymbolAddress((void**)&p_q, g_q);
    cudaGetSymbolAddress((void**)&p_k, g_k);
    cudaGetSymbolAddress((void**)&p_v, g_v);
    cudaGetSymbolAddress((void**)&p_sc, g_scores);
    cudaGetSymbolAddress((void**)&p_y, g_y);
    cudaGetSymbolAddress((void**)&p_x2, g_x2);
    cudaGetSymbolAddress((void**)&p_n2, g_n2);
    cudaGetSymbolAddress((void**)&p_gate, g_gate);
    cudaGetSymbolAddress((void**)&p_up, g_up);

    // 1. n1 = rmsnorm(x)
    rmsnorm_kernel<<<TSEQ, 256>>>(x, n1w, p_n1);
    // 2. qkv = n1 @ attn_w^T
    run_gemm<true, 0>(p_n1, attn_w, p_qkv, nullptr, TSEQ, QKVN, CEMB, QKVN, 0, 0, 0, 1, 1);
    // 3. scaling = relu(n1 @ scale_w^T + b)   [bias+relu fused]
    run_gemm<true, 2>(p_n1, scale_w, p_scaling, scale_b, TSEQ, CEMB, CEMB, CEMB, 0, 0, 0, 1, 1);
    // 4. scale_t[h][t]
    scale_reduce_kernel<<<TSEQ * NHEAD / 8, 256>>>(p_scaling, p_st);
    // 5. split + rope, fold sf*scale_t into q
    qkv_rope_kernel<<<TSEQ * 48 * HSZ / 256, 256>>>(p_qkv, cosp, sinp, p_st, p_q, p_k, p_v);
    // 6. scores[h] = q[h] @ k[h/4]^T
    run_gemm<true, 0>(p_q, p_k, p_sc, nullptr, TSEQ, TSEQ, HSZ, TSEQ,
                      (long long)TSEQ * HSZ, (long long)TSEQ * HSZ,
                      (long long)TSEQ * TSEQ, 4, NHEAD);
    // 7. softmax (2-pass, invsum deferred to AV epilogue)
    softmax_kernel<<<NHEAD * TSEQ, 256>>>(p_sc, p_is);
    // 8. y[h] = attn[h] @ v[h/4], row-scaled by invsum  [EPI=3]
    run_gemm<false, 3>(p_sc, p_v, p_y, p_is, TSEQ, HSZ, TSEQ, CEMB,
                       (long long)TSEQ * TSEQ, (long long)TSEQ * HSZ, HSZ, 4, NHEAD);
    // 9. x2 = y @ proj_w^T + x  [residual fused]
    run_gemm<true, 1>(p_y, proj_w, p_x2, x, TSEQ, CEMB, CEMB, CEMB, 0, 0, 0, 1, 1);
    // 10. n2 = rmsnorm(x2)
    rmsnorm_kernel<<<TSEQ, 256>>>(p_x2, n2w, p_n2);
    // 11. gate/up + silu*mul
    run_gemm<true, 0>(p_n2, gate_w, p_gate, nullptr, TSEQ, FFNN, CEMB, FFNN, 0, 0, 0, 1, 1);
    run_gemm<true, 0>(p_n2, up_w, p_up, nullptr, TSEQ, FFNN, CEMB, FFNN, 0, 0, 0, 1, 1);
    silu_mul_kernel<<<TSEQ * FFNN / 256, 256>>>(p_gate, p_up);
    // 12. out = act @ down_w^T + x2  [residual fused]
    run_gemm<true, 1>(p_gate, down_w, out, p_x2, TSEQ, CEMB, FFNN, CEMB, 0, 0, 0, 1, 1);
}

// round 8
// speedup vs baseline: 5.1020x; 3.3442x over previous
#include <cuda_runtime.h>
#include <cuda_fp16.h>
#include <mma.h>
#include <cstdint>

using namespace nvcuda;

#define TSEQ 2048
#define CEMB 4096
#define QKVN 6144
#define FFNN 11008
#define NHEAD 32
#define NGRP 8
#define HSZ 128

// ------------------------- scratch (device globals) -------------------------
// fp32
__device__ float g_qkv[TSEQ * QKVN];
__device__ float g_scaling[TSEQ * CEMB];
__device__ float g_scale_t[NHEAD * TSEQ];
__device__ float g_invsum[NHEAD * TSEQ];
__device__ float g_scores[134217728];            // 32 * 2048 * 2048 fp32
__device__ float g_x2[TSEQ * CEMB];
// fp16
__device__ __half g_n1h[TSEQ * CEMB];
__device__ __half g_n2h[TSEQ * CEMB];
__device__ __half g_qh[NHEAD * TSEQ * HSZ];
__device__ __half g_kh[NGRP * TSEQ * HSZ];
__device__ __half g_vh[NGRP * TSEQ * HSZ];
__device__ __half g_probs[134217728];            // 32 * 2048 * 2048 fp16
__device__ __half g_yh[TSEQ * CEMB];
__device__ __half g_uph[TSEQ * FFNN];
__device__ __half g_acth[TSEQ * FFNN];
// fp16 weights
__device__ __half g_wqkv[QKVN * CEMB];
__device__ __half g_wscale[CEMB * CEMB];
__device__ __half g_wproj[CEMB * CEMB];
__device__ __half g_wgate[FFNN * CEMB];
__device__ __half g_wup[FFNN * CEMB];
__device__ __half g_wdown[CEMB * FFNN];

// ------------------------- cp.async helpers -------------------------
__device__ __forceinline__ void cp_async16h(__half* smem, const __half* gmem)
{
    uint32_t s = (uint32_t)__cvta_generic_to_shared(smem);
    asm volatile("cp.async.cg.shared.global [%0], [%1], 16;\n" :: "r"(s), "l"(gmem));
}
#define CP_COMMIT asm volatile("cp.async.commit_group;\n" ::: "memory")

// ------------------------- GEMM (fp16 wmma, fp32 accum, 2-stage cp.async) ----
// C[M,N] = A[M,K] * op(B)  (+ epilogue)
//   TB=true : B is [N,K] row-major (B^T)   TB=false: B is [K,N] row-major
// EPI: 0=none  1=C+=epf[gm*ldc+gn]  2=C=relu(C+epf[gn])  3=C*=epf[z*M+gm]
//      4=C=silu(C)*eph[gm*ldc+gn]
#define BM 128
#define BN 128
#define BK 32
#define ALD 40       // halves; multiple of 8
#define BLDNN 136    // halves; multiple of 8
#define STAGE_H 10240            // halves per stage (A 5120 + B 5120)
#define GEMM_SMEM_BYTES 73728    // max(2*STAGE_H*2, 8*2304*4)
#define SLD 36

template <bool TB, int EPI, typename TO>
__global__ void __launch_bounds__(256, 2) hgemm(
    const __half* __restrict__ A, const __half* __restrict__ B, TO* __restrict__ C,
    const void* __restrict__ ep,
    int M, int N, int K, int ldc,
    long long sA, long long sB, long long sC, int bDiv)
{
    extern __shared__ __align__(16) char smraw[];
    __half* smh = (__half*)smraw;

    const int z = blockIdx.z;
    A += (long long)z * sA;
    B += (long long)(z / bDiv) * sB;
    C += (long long)z * sC;

    const int m0 = blockIdx.y * BM;
    const int n0 = blockIdx.x * BN;
    const int tid = threadIdx.x;
    const int lane = tid & 31;
    const int warp = tid >> 5;
    const int wr = warp >> 2;   // 0..1
    const int wc = warp & 3;    // 0..3

    const int ar = tid >> 2, ac = (tid & 3) << 3;     // [128][32] half tiles
    const int br = tid >> 4, bc = (tid & 15) << 3;    // [32][128] half tiles (NN)

    wmma::fragment<wmma::accumulator, 16, 16, 16, float> acc[4][2];
#pragma unroll
    for (int i = 0; i < 4; i++)
#pragma unroll
        for (int j = 0; j < 2; j++) wmma::fill_fragment(acc[i][j], 0.0f);

    const int KT = K >> 5;

    auto load_tile = [&](int kt, int st) {
        __half* As = smh + st * STAGE_H;
        __half* Bs = As + 5120;
        const int k0 = kt << 5;
#pragma unroll
        for (int it = 0; it < 2; it++) {
            int r = ar + it * 64;
            cp_async16h(As + r * ALD + ac, A + (long long)(m0 + r) * K + k0 + ac);
        }
        if (TB) {
#pragma unroll
            for (int it = 0; it < 2; it++) {
                int r = ar + it * 64;
                cp_async16h(Bs + r * ALD + ac, B + (long long)(n0 + r) * K + k0 + ac);
            }
        } else {
#pragma unroll
            for (int it = 0; it < 2; it++) {
                int r = br + it * 16;
                cp_async16h(Bs + r * BLDNN + bc, B + (long long)(k0 + r) * N + n0 + bc);
            }
        }
    };

    load_tile(0, 0);
    CP_COMMIT;

    for (int kt = 0; kt < KT; kt++) {
        const int cur = kt & 1;
        if (kt + 1 < KT) {
            load_tile(kt + 1, cur ^ 1);
            CP_COMMIT;
            asm volatile("cp.async.wait_group 1;\n" ::: "memory");
        } else {
            asm volatile("cp.async.wait_group 0;\n" ::: "memory");
        }
        __syncthreads();

        __half* As = smh + cur * STAGE_H;
        __half* Bs = As + 5120;
#pragma unroll
        for (int kk = 0; kk < 2; kk++) {
            wmma::fragment<wmma::matrix_a, 16, 16, 16, __half, wmma::row_major> fa[4];
#pragma unroll
            for (int i = 0; i < 4; i++)
                wmma::load_matrix_sync(fa[i], As + (wr * 64 + i * 16) * ALD + kk * 16, ALD);
            if (TB) {
                wmma::fragment<wmma::matrix_b, 16, 16, 16, __half, wmma::col_major> fb[2];
#pragma unroll
                for (int j = 0; j < 2; j++)
                    wmma::load_matrix_sync(fb[j], Bs + (wc * 32 + j * 16) * ALD + kk * 16, ALD);
#pragma unroll
                for (int i = 0; i < 4; i++)
#pragma unroll
                    for (int j = 0; j < 2; j++)
                        wmma::mma_sync(acc[i][j], fa[i], fb[j], acc[i][j]);
            } else {
                wmma::fragment<wmma::matrix_b, 16, 16, 16, __half, wmma::row_major> fb[2];
#pragma unroll
                for (int j = 0; j < 2; j++)
                    wmma::load_matrix_sync(fb[j], Bs + (kk * 16) * BLDNN + wc * 32 + j * 16, BLDNN);
#pragma unroll
                for (int i = 0; i < 4; i++)
#pragma unroll
                    for (int j = 0; j < 2; j++)
                        wmma::mma_sync(acc[i][j], fa[i], fb[j], acc[i][j]);
            }
        }
        __syncthreads();
    }

    // ---- epilogue via smem staging (64 x SLD floats per warp) ----
    float* stg = (float*)smraw + warp * (64 * SLD);
#pragma unroll
    for (int i = 0; i < 4; i++)
#pragma unroll
        for (int j = 0; j < 2; j++)
            wmma::store_matrix_sync(stg + (i * 16) * SLD + j * 16, acc[i][j], SLD,
                                    wmma::mem_row_major);
    __syncwarp();

    const float* epf = (const float*)ep;
    const __half* eph = (const __half*)ep;
    const int gn = n0 + wc * 32 + lane;
#pragma unroll 4
    for (int r = 0; r < 64; r++) {
        const int gm = m0 + wr * 64 + r;
        float v = stg[r * SLD + lane];
        if (EPI == 1) v += epf[(long long)gm * ldc + gn];
        if (EPI == 2) v = fmaxf(v + epf[gn], 0.0f);
        if (EPI == 3) v *= epf[(long long)z * M + gm];
        if (EPI == 4) v = (v / (1.f + __expf(-v))) * __half2float(eph[(long long)gm * ldc + gn]);
        if (sizeof(TO) == 2)
            ((__half*)C)[(long long)gm * ldc + gn] = __float2half(v);
        else
            ((float*)C)[(long long)gm * ldc + gn] = v;
    }
}

// ------------------------- small kernels -------------------------

__global__ void w2h_kernel(const float* __restrict__ in, __half* __restrict__ out)
{
    const long long i = ((long long)blockIdx.x * 256 + threadIdx.x) * 4;
    float4 v = *(const float4*)(in + i);
    __half2* o = (__half2*)(out + i);
    o[0] = __floats2half2_rn(v.x, v.y);
    o[1] = __floats2half2_rn(v.z, v.w);
}

__global__ void rmsnorm_kernel(const float* __restrict__ x, const float* __restrict__ w,
                               __half* __restrict__ out)
{
    __shared__ float red[256];
    const int t = blockIdx.x;
    const float* row = x + (size_t)t * CEMB;
    __half* orow = out + (size_t)t * CEMB;
    const int tid = threadIdx.x;
    float s = 0.f;
    for (int i = tid; i < CEMB; i += 256) { float v = row[i]; s += v * v; }
    red[tid] = s;
    __syncthreads();
    for (int st = 128; st > 0; st >>= 1) {
        if (tid < st) red[tid] += red[tid + st];
        __syncthreads();
    }
    const float inv = rsqrtf(red[0] * (1.0f / CEMB) + 1e-5f);
    for (int i = tid; i < CEMB; i += 256) orow[i] = __float2half(row[i] * inv * w[i]);
}

__global__ void scale_reduce_kernel(const float* __restrict__ s, float* __restrict__ st)
{
    const int pair = blockIdx.x * 8 + (threadIdx.x >> 5);  // = t*32 + h
    const int lane = threadIdx.x & 31;
    const int t = pair >> 5;
    const int h = pair & 31;
    const float* p = s + (size_t)t * CEMB + h * HSZ;
    float acc = 0.f;
    for (int d = lane; d < HSZ; d += 32) acc += p[d];
    for (int o = 16; o; o >>= 1) acc += __shfl_down_sync(0xffffffffu, acc, o);
    if (lane == 0) st[h * TSEQ + t] = acc * (1.0f / HSZ);
}

__global__ void qkv_rope_kernel(const float* __restrict__ qkv, const float* __restrict__ cs,
                                const float* __restrict__ sn, const float* __restrict__ st,
                                __half* __restrict__ q, __half* __restrict__ k,
                                __half* __restrict__ v)
{
    const int idx = blockIdx.x * 256 + threadIdx.x;
    const int d = idx & 127;
    const int rest = idx >> 7;
    const int slot = rest % 48;
    const int t = rest / 48;
    const int g = slot / 6;
    const int i = slot % 6;
    const float* src = qkv + (size_t)t * QKVN + g * 768 + i * 128;
    const float x0 = src[d];
    if (i == 5) {
        v[((size_t)g * TSEQ + t) * HSZ + d] = __float2half(x0);
        return;
    }
    const float xp = src[d ^ 64];
    const float rot = (d < 64) ? -xp : xp;
    const float val = x0 * cs[t * 128 + d] + rot * sn[t * 128 + d];
    if (i == 4) {
        k[((size_t)g * TSEQ + t) * HSZ + d] = __float2half(val);
    } else {
        const int h = g * 4 + i;
        q[((size_t)h * TSEQ + t) * HSZ + d] =
            __float2half(val * (0.08838834764831845f * st[h * TSEQ + t]));
    }
}

// softmax: read fp32 scores, write fp16 exp(x-max) probs + fp32 invsum
__global__ void softmax_kernel(const float* __restrict__ scores, __half* __restrict__ probs,
                               float* __restrict__ invsum)
{
    __shared__ float red[256];
    const size_t row = blockIdx.x;
    const float* p = scores + row * TSEQ;
    __half* ph = probs + row * TSEQ;
    const int tid = threadIdx.x;

    float m = -1e30f;
    for (int i = tid; i < TSEQ; i += 256) m = fmaxf(m, p[i]);
    red[tid] = m;
    __syncthreads();
    for (int st = 128; st > 0; st >>= 1) {
        if (tid < st) red[tid] = fmaxf(red[tid], red[tid + st]);
        __syncthreads();
    }
    m = red[0];
    __syncthreads();

    float sum = 0.f;
    for (int i = tid; i < TSEQ; i += 256) {
        float e = __expf(p[i] - m);
        ph[i] = __float2half(e);
        sum += e;
    }
    red[tid] = sum;
    __syncthreads();
    for (int st = 128; st > 0; st >>= 1) {
        if (tid < st) red[tid] += red[tid + st];
        __syncthreads();
    }
    if (tid == 0) invsum[row] = 1.f / red[0];
}

// ------------------------- host side -------------------------

template <bool TB, int EPI, typename TO>
static inline void run_gemm(const __half* A, const __half* B, TO* C, const void* ep,
                            int M, int N, int K, int ldc,
                            long long sA, long long sB, long long sC, int bDiv, int nb)
{
    cudaFuncSetAttribute(hgemm<TB, EPI, TO>,
                         cudaFuncAttributeMaxDynamicSharedMemorySize, GEMM_SMEM_BYTES);
    dim3 grid(N / BN, M / BM, nb);
    hgemm<TB, EPI, TO><<<grid, 256, GEMM_SMEM_BYTES>>>(A, B, C, ep, M, N, K, ldc,
                                                       sA, sB, sC, bDiv);
}

static inline void conv_w(const float* in, __half* out, long long n)
{
    w2h_kernel<<<(unsigned)(n / 1024), 256>>>(in, out);
}

extern "C" void kernel_launch(void* const* d_in, const int* in_sizes, int n_in,
                              void* d_out, int out_size)
{
    (void)in_sizes; (void)n_in; (void)out_size;
    const float* x       = (const float*)d_in[0];
    const float* cosp    = (const float*)d_in[1];
    const float* sinp    = (const float*)d_in[2];
    const float* n1w     = (const float*)d_in[3];
    const float* n2w     = (const float*)d_in[4];
    const float* attn_w  = (const float*)d_in[5];
    const float* proj_w  = (const float*)d_in[6];
    const float* scale_w = (const float*)d_in[7];
    const float* scale_b = (const float*)d_in[8];
    const float* gate_w  = (const float*)d_in[9];
    const float* up_w    = (const float*)d_in[10];
    const float* down_w  = (const float*)d_in[11];
    float* out = (float*)d_out;

    float *p_qkv, *p_scaling, *p_st, *p_is, *p_sc, *p_x2;
    __half *p_n1h, *p_n2h, *p_qh, *p_kh, *p_vh, *p_probs, *p_yh, *p_uph, *p_acth;
    __half *p_wqkv, *p_wscale, *p_wproj, *p_wgate, *p_wup, *p_wdown;
    cudaGetSymbolAddress((void**)&p_qkv, g_qkv);
    cudaGetSymbolAddress((void**)&p_scaling, g_scaling);
    cudaGetSymbolAddress((void**)&p_st, g_scale_t);
    cudaGetSymbolAddress((void**)&p_is, g_invsum);
    cudaGetSymbolAddress((void**)&p_sc, g_scores);
    cudaGetSymbolAddress((void**)&p_x2, g_x2);
    cudaGetSymbolAddress((void**)&p_n1h, g_n1h);
    cudaGetSymbolAddress((void**)&p_n2h, g_n2h);
    cudaGetSymbolAddress((void**)&p_qh, g_qh);
    cudaGetSymbolAddress((void**)&p_kh, g_kh);
    cudaGetSymbolAddress((void**)&p_vh, g_vh);
    cudaGetSymbolAddress((void**)&p_probs, g_probs);
    cudaGetSymbolAddress((void**)&p_yh, g_yh);
    cudaGetSymbolAddress((void**)&p_uph, g_uph);
    cudaGetSymbolAddress((void**)&p_acth, g_acth);
    cudaGetSymbolAddress((void**)&p_wqkv, g_wqkv);
    cudaGetSymbolAddress((void**)&p_wscale, g_wscale);
    cudaGetSymbolAddress((void**)&p_wproj, g_wproj);
    cudaGetSymbolAddress((void**)&p_wgate, g_wgate);
    cudaGetSymbolAddress((void**)&p_wup, g_wup);
    cudaGetSymbolAddress((void**)&p_wdown, g_wdown);

    // 0. convert weights to fp16
    conv_w(attn_w,  p_wqkv,   (long long)QKVN * CEMB);
    conv_w(scale_w, p_wscale, (long long)CEMB * CEMB);
    conv_w(proj_w,  p_wproj,  (long long)CEMB * CEMB);
    conv_w(gate_w,  p_wgate,  (long long)FFNN * CEMB);
    conv_w(up_w,    p_wup,    (long long)FFNN * CEMB);
    conv_w(down_w,  p_wdown,  (long long)CEMB * FFNN);

    // 1. n1 = rmsnorm(x) -> fp16
    rmsnorm_kernel<<<TSEQ, 256>>>(x, n1w, p_n1h);
    // 2. qkv = n1 @ attn_w^T  (fp32 out, feeds rope)
    run_gemm<true, 0, float>(p_n1h, p_wqkv, p_qkv, nullptr, TSEQ, QKVN, CEMB, QKVN,
                             0, 0, 0, 1, 1);
    // 3. scaling = relu(n1 @ scale_w^T + b)
    run_gemm<true, 2, float>(p_n1h, p_wscale, p_scaling, scale_b, TSEQ, CEMB, CEMB, CEMB,
                             0, 0, 0, 1, 1);
    // 4. scale_t[h][t]
    scale_reduce_kernel<<<TSEQ * NHEAD / 8, 256>>>(p_scaling, p_st);
    // 5. split + rope (fold sf*scale_t into q), fp16 out
    qkv_rope_kernel<<<TSEQ * 48 * HSZ / 256, 256>>>(p_qkv, cosp, sinp, p_st, p_qh, p_kh, p_vh);
    // 6. scores[h] = q[h] @ k[h/4]^T  (fp32 out)
    run_gemm<true, 0, float>(p_qh, p_kh, p_sc, nullptr, TSEQ, TSEQ, HSZ, TSEQ,
                             (long long)TSEQ * HSZ, (long long)TSEQ * HSZ,
                             (long long)TSEQ * TSEQ, 4, NHEAD);
    // 7. softmax -> fp16 probs + fp32 invsum
    softmax_kernel<<<NHEAD * TSEQ, 256>>>(p_sc, p_probs, p_is);
    // 8. y[h] = probs[h] @ v[h/4] * invsum  (fp16 out, interleaved [t, h*128+d])
    run_gemm<false, 3, __half>(p_probs, p_vh, p_yh, p_is, TSEQ, HSZ, TSEQ, CEMB,
                               (long long)TSEQ * TSEQ, (long long)TSEQ * HSZ, HSZ, 4, NHEAD);
    // 9. x2 = y @ proj_w^T + x  (fp32 out)
    run_gemm<true, 1, float>(p_yh, p_wproj, p_x2, x, TSEQ, CEMB, CEMB, CEMB, 0, 0, 0, 1, 1);
    // 10. n2 = rmsnorm(x2) -> fp16
    rmsnorm_kernel<<<TSEQ, 256>>>(p_x2, n2w, p_n2h);
    // 11. up, then gate with fused silu(gate)*up  (fp16 outs)
    run_gemm<true, 0, __half>(p_n2h, p_wup, p_uph, nullptr, TSEQ, FFNN, CEMB, FFNN,
                              0, 0, 0, 1, 1);
    run_gemm<true, 4, __half>(p_n2h, p_wgate, p_acth, p_uph, TSEQ, FFNN, CEMB, FFNN,
                              0, 0, 0, 1, 1);
    // 12. out = act @ down_w^T + x2  (fp32 out)
    run_gemm<true, 1, float>(p_acth, p_wdown, out, p_x2, TSEQ, CEMB, FFNN, CEMB,
                             0, 0, 0, 1, 1);
}